// round 5
// baseline (speedup 1.0000x reference)
#include <cuda_runtime.h>
#include <cuda_bf16.h>
#include <math.h>
#include <stdint.h>

#define HID 128
#define TILE 256           // edges per CTA
#define NTHREADS 512       // 16 warps x 16 edges
#define IN_SZ 9
#define H0S 136            // h0 smem row stride (floats), conflict-free frag reads
#define SMEM_BYTES (TILE * H0S * 4 + TILE * 4)

// Pre-packed weight fragments for w1..w3:
// g_wb[L][q][nt][lane] = uint4 {bhi_r0, bhi_r1, blo_r0, blo_r1}
// (m16n8k16 B-frag: r0 -> k = 16q + 2t + {0,1}, r1 -> k = 16q + 2t + 8 + {0,1}, n = 8nt + g)
__device__ uint4 g_wb[3 * 8 * 16 * 32];

__device__ __forceinline__ void split2(float v0, float v1, uint32_t& hi, uint32_t& lo) {
    __nv_bfloat16 h0 = __float2bfloat16_rn(v0);
    __nv_bfloat16 h1 = __float2bfloat16_rn(v1);
    float r0 = v0 - __bfloat162float(h0);
    float r1 = v1 - __bfloat162float(h1);
    hi = (uint32_t)__bfloat16_as_ushort(h0) | ((uint32_t)__bfloat16_as_ushort(h1) << 16);
    lo = (uint32_t)__bfloat16_as_ushort(__float2bfloat16_rn(r0))
       | ((uint32_t)__bfloat16_as_ushort(__float2bfloat16_rn(r1)) << 16);
}

__device__ __forceinline__ void mma16816(float* d,
                                         uint32_t a0, uint32_t a1, uint32_t a2, uint32_t a3,
                                         uint32_t b0, uint32_t b1) {
    asm volatile(
        "mma.sync.aligned.m16n8k16.row.col.f32.bf16.bf16.f32 "
        "{%0,%1,%2,%3}, {%4,%5,%6,%7}, {%8,%9}, {%0,%1,%2,%3};"
        : "+f"(d[0]), "+f"(d[1]), "+f"(d[2]), "+f"(d[3])
        : "r"(a0), "r"(a1), "r"(a2), "r"(a3), "r"(b0), "r"(b1));
}

// One hidden layer: Aout = relu(Ain @ W + b), processed in two n-halves (D[8][4] live).
__device__ __forceinline__ void hidden_layer(
    uint32_t (&AinHi)[8][4], uint32_t (&AinLo)[8][4],
    uint32_t (&AoutHi)[8][4], uint32_t (&AoutLo)[8][4],
    const uint4* __restrict__ wbL, const float* __restrict__ bL,
    int lane, int t)
{
    #pragma unroll
    for (int jh = 0; jh < 2; jh++) {
        float D[8][4];
        #pragma unroll
        for (int j = 0; j < 8; j++) {
            D[j][0] = 0.f; D[j][1] = 0.f; D[j][2] = 0.f; D[j][3] = 0.f;
        }
        #pragma unroll
        for (int q = 0; q < 8; q++) {
            #pragma unroll
            for (int j = 0; j < 8; j++) {
                uint4 B = wbL[(q * 16 + jh * 8 + j) * 32 + lane];
                mma16816(D[j], AinHi[q][0], AinHi[q][1], AinHi[q][2], AinHi[q][3], B.x, B.y);
                mma16816(D[j], AinHi[q][0], AinHi[q][1], AinHi[q][2], AinHi[q][3], B.z, B.w);
                mma16816(D[j], AinLo[q][0], AinLo[q][1], AinLo[q][2], AinLo[q][3], B.x, B.y);
            }
        }
        // epilogue for chunks qo = 4*jh + jj
        #pragma unroll
        for (int jj = 0; jj < 4; jj++) {
            int qo = 4 * jh + jj;
            int j0 = 2 * jj, j1 = 2 * jj + 1;
            float2 bj0 = *(const float2*)(bL + (8 * jh + j0) * 8 + t * 2);
            float2 bj1 = *(const float2*)(bL + (8 * jh + j1) * 8 + t * 2);
            float v0 = fmaxf(D[j0][0] + bj0.x, 0.f);
            float v1 = fmaxf(D[j0][1] + bj0.y, 0.f);
            float v2 = fmaxf(D[j0][2] + bj0.x, 0.f);
            float v3 = fmaxf(D[j0][3] + bj0.y, 0.f);
            split2(v0, v1, AoutHi[qo][0], AoutLo[qo][0]);
            split2(v2, v3, AoutHi[qo][1], AoutLo[qo][1]);
            float u0 = fmaxf(D[j1][0] + bj1.x, 0.f);
            float u1 = fmaxf(D[j1][1] + bj1.y, 0.f);
            float u2 = fmaxf(D[j1][2] + bj1.x, 0.f);
            float u3 = fmaxf(D[j1][3] + bj1.y, 0.f);
            split2(u0, u1, AoutHi[qo][2], AoutLo[qo][2]);
            split2(u2, u3, AoutHi[qo][3], AoutLo[qo][3]);
        }
    }
}

// ---------------- prep: pack w1..w3 into mma B-fragment layout ----------------
__global__ void prep_kernel(const float* __restrict__ w1,
                            const float* __restrict__ w2,
                            const float* __restrict__ w3) {
    int s = blockIdx.x * blockDim.x + threadIdx.x;
    if (s >= 3 * 8 * 16 * 32) return;
    int lane = s & 31;
    int nt   = (s >> 5) & 15;
    int q    = (s >> 9) & 7;
    int L    = s >> 12;
    int g = lane >> 2, t = lane & 3;
    int n  = nt * 8 + g;
    int k0 = q * 16 + t * 2;
    const float* W = (L == 0) ? w1 : (L == 1) ? w2 : w3;
    float v00 = W[k0 * HID + n];
    float v01 = W[(k0 + 1) * HID + n];
    float v10 = W[(k0 + 8) * HID + n];
    float v11 = W[(k0 + 9) * HID + n];
    uint4 o;
    split2(v00, v01, o.x, o.z);
    split2(v10, v11, o.y, o.w);
    g_wb[s] = o;
}

__global__ void zero_kernel(float* __restrict__ out, int n) {
    int i = blockIdx.x * blockDim.x + threadIdx.x;
    if (i < n) out[i] = 0.0f;
}

// ---------------- main kernel ----------------
__global__ __launch_bounds__(NTHREADS, 1)
void gnn_mma_kernel(
    const float* __restrict__ pos,
    const float* __restrict__ vel,
    const float* __restrict__ a,
    const float* __restrict__ vnorm,
    const float* __restrict__ w0, const float* __restrict__ b0,
    const float* __restrict__ b1, const float* __restrict__ b2, const float* __restrict__ b3,
    const float* __restrict__ w4, const float* __restrict__ b4,
    const int* __restrict__ ei,
    const int* __restrict__ data_id_p,
    float* __restrict__ out,
    int E, int N)
{
    extern __shared__ float sm[];
    float* h0s  = sm;                        // [TILE][H0S]
    int*   sdst = (int*)(sm + TILE * H0S);   // [TILE]

    const int tid  = threadIdx.x;
    const int warp = tid >> 5;
    const int lane = tid & 31;
    const int g = lane >> 2, t = lane & 3;

    // ---- layer 0 (SIMT fp32): 2 threads per edge, 64 cols each ----
    {
        int e_loc = tid >> 1;
        int cb    = (tid & 1) * 64;
        int e     = blockIdx.x * TILE + e_loc;
        float f[IN_SZ];
        int dstv = -1;
        if (e < E) {
            dstv    = ei[e];
            int src = ei[E + e];
            float inv_vn = 1.0f / vnorm[0];
            float dpx = (pos[2 * src]     - pos[2 * dstv])     * 10.0f;  // / MAX_RADIUS
            float dpy = (pos[2 * src + 1] - pos[2 * dstv + 1]) * 10.0f;
            f[0] = dpx; f[1] = dpy;
            f[2] = sqrtf(dpx * dpx + dpy * dpy);
            f[3] = vel[2 * dstv]     * inv_vn;
            f[4] = vel[2 * dstv + 1] * inv_vn;
            f[5] = vel[2 * src]      * inv_vn;
            f[6] = vel[2 * src + 1]  * inv_vn;
            int did = *data_id_p;
            const float* emb = a + ((size_t)did * N + dstv) * 2;
            f[7] = emb[0]; f[8] = emb[1];
        } else {
            #pragma unroll
            for (int k = 0; k < IN_SZ; k++) f[k] = 0.0f;
        }
        if ((tid & 1) == 0) sdst[e_loc] = dstv;

        float* hr = h0s + e_loc * H0S;
        #pragma unroll
        for (int c0 = 0; c0 < 64; c0 += 4) {
            int c = cb + c0;
            float4 acc = *(const float4*)(b0 + c);
            #pragma unroll
            for (int k = 0; k < IN_SZ; k++) {
                float4 w = *(const float4*)(w0 + k * HID + c);
                acc.x = fmaf(f[k], w.x, acc.x);
                acc.y = fmaf(f[k], w.y, acc.y);
                acc.z = fmaf(f[k], w.z, acc.z);
                acc.w = fmaf(f[k], w.w, acc.w);
            }
            float4 v;
            v.x = fmaxf(acc.x, 0.0f);
            v.y = fmaxf(acc.y, 0.0f);
            v.z = fmaxf(acc.z, 0.0f);
            v.w = fmaxf(acc.w, 0.0f);
            *(float4*)(hr + c) = v;
        }
    }
    __syncthreads();

    // ---- build layer-1 A fragments from h0 (warp-local rows) ----
    uint32_t Ahi[8][4], Alo[8][4];     // ping
    uint32_t Bhi[8][4], Blo[8][4];     // pong
    {
        const float* r0p = h0s + (warp * 16 + g)     * H0S;
        const float* r1p = h0s + (warp * 16 + g + 8) * H0S;
        #pragma unroll
        for (int q = 0; q < 8; q++) {
            int c = 16 * q + 2 * t;
            float2 p0 = *(const float2*)(r0p + c);
            float2 p1 = *(const float2*)(r1p + c);
            float2 p2 = *(const float2*)(r0p + c + 8);
            float2 p3 = *(const float2*)(r1p + c + 8);
            split2(p0.x, p0.y, Ahi[q][0], Alo[q][0]);
            split2(p1.x, p1.y, Ahi[q][1], Alo[q][1]);
            split2(p2.x, p2.y, Ahi[q][2], Alo[q][2]);
            split2(p3.x, p3.y, Ahi[q][3], Alo[q][3]);
        }
    }

    // ---- hidden layers 1 and 2: ping-pong in registers ----
    hidden_layer(Ahi, Alo, Bhi, Blo, g_wb,                  b1, lane, t);
    hidden_layer(Bhi, Blo, Ahi, Alo, g_wb + 8 * 16 * 32,    b2, lane, t);

    // ---- layer 3 (w3) + fused layer 4 (w4) + scatter ----
    {
        const uint4* wbL = g_wb + (size_t)2 * (8 * 16 * 32);
        float m0g = 0.f, m1g = 0.f, m0h = 0.f, m1h = 0.f;
        #pragma unroll
        for (int jh = 0; jh < 2; jh++) {
            float D[8][4];
            #pragma unroll
            for (int j = 0; j < 8; j++) {
                D[j][0] = 0.f; D[j][1] = 0.f; D[j][2] = 0.f; D[j][3] = 0.f;
            }
            #pragma unroll
            for (int q = 0; q < 8; q++) {
                #pragma unroll
                for (int j = 0; j < 8; j++) {
                    uint4 B = wbL[(q * 16 + jh * 8 + j) * 32 + lane];
                    mma16816(D[j], Ahi[q][0], Ahi[q][1], Ahi[q][2], Ahi[q][3], B.x, B.y);
                    mma16816(D[j], Ahi[q][0], Ahi[q][1], Ahi[q][2], Ahi[q][3], B.z, B.w);
                    mma16816(D[j], Alo[q][0], Alo[q][1], Alo[q][2], Alo[q][3], B.x, B.y);
                }
            }
            #pragma unroll
            for (int j = 0; j < 8; j++) {
                int nt = 8 * jh + j;
                float2 bj = *(const float2*)(b3 + nt * 8 + t * 2);
                float v0 = fmaxf(D[j][0] + bj.x, 0.f);
                float v1 = fmaxf(D[j][1] + bj.y, 0.f);
                float v2 = fmaxf(D[j][2] + bj.x, 0.f);
                float v3 = fmaxf(D[j][3] + bj.y, 0.f);
                float4 w4v = *(const float4*)(w4 + 2 * (nt * 8 + t * 2));  // w4[2k..2k+3]
                m0g = fmaf(v0, w4v.x, fmaf(v1, w4v.z, m0g));
                m1g = fmaf(v0, w4v.y, fmaf(v1, w4v.w, m1g));
                m0h = fmaf(v2, w4v.x, fmaf(v3, w4v.z, m0h));
                m1h = fmaf(v2, w4v.y, fmaf(v3, w4v.w, m1h));
            }
        }
        // reduce across the quad (t = 0..3)
        #pragma unroll
        for (int d = 1; d <= 2; d <<= 1) {
            m0g += __shfl_xor_sync(0xFFFFFFFFu, m0g, d);
            m1g += __shfl_xor_sync(0xFFFFFFFFu, m1g, d);
            m0h += __shfl_xor_sync(0xFFFFFFFFu, m0h, d);
            m1h += __shfl_xor_sync(0xFFFFFFFFu, m1h, d);
        }
        if (t == 0) {
            float bb0 = b4[0], bb1 = b4[1];
            int d0 = sdst[warp * 16 + g];
            if (d0 >= 0) {
                atomicAdd(&out[2 * d0],     m0g + bb0);
                atomicAdd(&out[2 * d0 + 1], m1g + bb1);
            }
            int d1 = sdst[warp * 16 + g + 8];
            if (d1 >= 0) {
                atomicAdd(&out[2 * d1],     m0h + bb0);
                atomicAdd(&out[2 * d1 + 1], m1h + bb1);
            }
        }
    }
}

extern "C" void kernel_launch(void* const* d_in, const int* in_sizes, int n_in,
                              void* d_out, int out_size) {
    const float* pos   = (const float*)d_in[0];
    const float* vel   = (const float*)d_in[1];
    const float* a     = (const float*)d_in[2];
    const float* vnorm = (const float*)d_in[3];
    const float* w0    = (const float*)d_in[4];
    const float* b0    = (const float*)d_in[5];
    const float* w1    = (const float*)d_in[6];
    const float* b1    = (const float*)d_in[7];
    const float* w2    = (const float*)d_in[8];
    const float* b2    = (const float*)d_in[9];
    const float* w3    = (const float*)d_in[10];
    const float* b3    = (const float*)d_in[11];
    const float* w4    = (const float*)d_in[12];
    const float* b4    = (const float*)d_in[13];
    const int*   ei    = (const int*)d_in[14];    // int32 [2, E]
    const int*   did   = (const int*)d_in[15];
    float*       out   = (float*)d_out;

    int E = in_sizes[14] / 2;
    int N = in_sizes[0] / 2;

    cudaFuncSetAttribute(gnn_mma_kernel,
                         cudaFuncAttributeMaxDynamicSharedMemorySize, SMEM_BYTES);

    prep_kernel<<<(3 * 8 * 16 * 32 + 255) / 256, 256>>>(w1, w2, w3);
    zero_kernel<<<(out_size + 255) / 256, 256>>>(out, out_size);

    int tiles = (E + TILE - 1) / TILE;
    gnn_mma_kernel<<<tiles, NTHREADS, SMEM_BYTES>>>(
        pos, vel, a, vnorm, w0, b0, b1, b2, b3, w4, b4,
        ei, did, out, E, N);
}

// round 6
// speedup vs baseline: 1.0520x; 1.0520x over previous
#include <cuda_runtime.h>
#include <cuda_bf16.h>
#include <math.h>
#include <stdint.h>

#define HID 128
#define TILE 128           // edges per CTA
#define NTHREADS 256       // 8 warps x 16 edges
#define IN_SZ 9
#define H0S 136            // h0 smem row stride (floats)
#define SMEM_BYTES (TILE * H0S * 4 + TILE * 4)
#define NFRAG (3 * 8 * 16 * 32)

// Pre-packed weight fragments for w1..w3:
// g_wb[L][q][nt][lane] = uint4 {bhi_r0, bhi_r1, blo_r0, blo_r1}
// (m16n8k16 B-frag: r0 -> k = 16q + 2t + {0,1}, r1 -> k = 16q + 2t + 8 + {0,1}, n = 8nt + g)
__device__ uint4 g_wb[NFRAG];

__device__ __forceinline__ void split2(float v0, float v1, uint32_t& hi, uint32_t& lo) {
    __nv_bfloat16 h0 = __float2bfloat16_rn(v0);
    __nv_bfloat16 h1 = __float2bfloat16_rn(v1);
    float r0 = v0 - __bfloat162float(h0);
    float r1 = v1 - __bfloat162float(h1);
    hi = (uint32_t)__bfloat16_as_ushort(h0) | ((uint32_t)__bfloat16_as_ushort(h1) << 16);
    lo = (uint32_t)__bfloat16_as_ushort(__float2bfloat16_rn(r0))
       | ((uint32_t)__bfloat16_as_ushort(__float2bfloat16_rn(r1)) << 16);
}

__device__ __forceinline__ void mma16816(float* d,
                                         uint32_t a0, uint32_t a1, uint32_t a2, uint32_t a3,
                                         uint32_t b0, uint32_t b1) {
    asm volatile(
        "mma.sync.aligned.m16n8k16.row.col.f32.bf16.bf16.f32 "
        "{%0,%1,%2,%3}, {%4,%5,%6,%7}, {%8,%9}, {%0,%1,%2,%3};"
        : "+f"(d[0]), "+f"(d[1]), "+f"(d[2]), "+f"(d[3])
        : "r"(a0), "r"(a1), "r"(a2), "r"(a3), "r"(b0), "r"(b1));
}

// MMA core for one layer: D[16][4] += split-product, interleaved passes
// (8 independent MMAs between touches of the same accumulator).
__device__ __forceinline__ void layer_mma(
    float (&D)[16][4],
    const uint32_t (&Ahi)[8][4], const uint32_t (&Alo)[8][4],
    const uint4* __restrict__ wbL, int lane)
{
    #pragma unroll
    for (int q = 0; q < 8; q++) {
        #pragma unroll
        for (int jb = 0; jb < 2; jb++) {
            uint4 B[8];
            #pragma unroll
            for (int j = 0; j < 8; j++) B[j] = wbL[(q * 16 + jb * 8 + j) * 32 + lane];
            #pragma unroll
            for (int j = 0; j < 8; j++)
                mma16816(D[jb * 8 + j], Ahi[q][0], Ahi[q][1], Ahi[q][2], Ahi[q][3], B[j].x, B[j].y);
            #pragma unroll
            for (int j = 0; j < 8; j++)
                mma16816(D[jb * 8 + j], Ahi[q][0], Ahi[q][1], Ahi[q][2], Ahi[q][3], B[j].z, B[j].w);
            #pragma unroll
            for (int j = 0; j < 8; j++)
                mma16816(D[jb * 8 + j], Alo[q][0], Alo[q][1], Alo[q][2], Alo[q][3], B[j].x, B[j].y);
        }
    }
}

// ---------------- prep (+ output zeroing, merged to keep launch count at 2) ----------------
__global__ void prep_kernel(const float* __restrict__ w1,
                            const float* __restrict__ w2,
                            const float* __restrict__ w3,
                            float* __restrict__ out, int out_n) {
    int s = blockIdx.x * blockDim.x + threadIdx.x;
    if (s < out_n) out[s] = 0.0f;
    if (s >= NFRAG) return;
    int lane = s & 31;
    int nt   = (s >> 5) & 15;
    int q    = (s >> 9) & 7;
    int L    = s >> 12;
    int g = lane >> 2, t = lane & 3;
    int n  = nt * 8 + g;
    int k0 = q * 16 + t * 2;
    const float* W = (L == 0) ? w1 : (L == 1) ? w2 : w3;
    float v00 = W[k0 * HID + n];
    float v01 = W[(k0 + 1) * HID + n];
    float v10 = W[(k0 + 8) * HID + n];
    float v11 = W[(k0 + 9) * HID + n];
    uint4 o;
    split2(v00, v01, o.x, o.z);
    split2(v10, v11, o.y, o.w);
    g_wb[s] = o;
}

// ---------------- main kernel ----------------
__global__ __launch_bounds__(NTHREADS, 1)
void gnn_mma_kernel(
    const float* __restrict__ pos,
    const float* __restrict__ vel,
    const float* __restrict__ a,
    const float* __restrict__ vnorm,
    const float* __restrict__ w0, const float* __restrict__ b0,
    const float* __restrict__ b1, const float* __restrict__ b2, const float* __restrict__ b3,
    const float* __restrict__ w4, const float* __restrict__ b4,
    const int* __restrict__ ei,
    const int* __restrict__ data_id_p,
    float* __restrict__ out,
    int E, int N)
{
    extern __shared__ float sm[];
    float* h0s  = sm;                        // [TILE][H0S]
    int*   sdst = (int*)(sm + TILE * H0S);   // [TILE]

    const int tid  = threadIdx.x;
    const int warp = tid >> 5;
    const int lane = tid & 31;
    const int g = lane >> 2, t = lane & 3;

    // ---- layer 0 (SIMT fp32): 2 threads per edge, 64 cols each ----
    {
        int e_loc = tid >> 1;
        int cb    = (tid & 1) * 64;
        int e     = blockIdx.x * TILE + e_loc;
        float f[IN_SZ];
        int dstv = -1;
        if (e < E) {
            dstv    = ei[e];
            int src = ei[E + e];
            float inv_vn = 1.0f / vnorm[0];
            float dpx = (pos[2 * src]     - pos[2 * dstv])     * 10.0f;  // / MAX_RADIUS
            float dpy = (pos[2 * src + 1] - pos[2 * dstv + 1]) * 10.0f;
            f[0] = dpx; f[1] = dpy;
            f[2] = sqrtf(dpx * dpx + dpy * dpy);
            f[3] = vel[2 * dstv]     * inv_vn;
            f[4] = vel[2 * dstv + 1] * inv_vn;
            f[5] = vel[2 * src]      * inv_vn;
            f[6] = vel[2 * src + 1]  * inv_vn;
            int did = *data_id_p;
            const float* emb = a + ((size_t)did * N + dstv) * 2;
            f[7] = emb[0]; f[8] = emb[1];
        } else {
            #pragma unroll
            for (int k = 0; k < IN_SZ; k++) f[k] = 0.0f;
        }
        if ((tid & 1) == 0) sdst[e_loc] = dstv;

        float* hr = h0s + e_loc * H0S;
        #pragma unroll
        for (int c0 = 0; c0 < 64; c0 += 4) {
            int c = cb + c0;
            float4 acc = *(const float4*)(b0 + c);
            #pragma unroll
            for (int k = 0; k < IN_SZ; k++) {
                float4 w = *(const float4*)(w0 + k * HID + c);
                acc.x = fmaf(f[k], w.x, acc.x);
                acc.y = fmaf(f[k], w.y, acc.y);
                acc.z = fmaf(f[k], w.z, acc.z);
                acc.w = fmaf(f[k], w.w, acc.w);
            }
            float4 v;
            v.x = fmaxf(acc.x, 0.0f);
            v.y = fmaxf(acc.y, 0.0f);
            v.z = fmaxf(acc.z, 0.0f);
            v.w = fmaxf(acc.w, 0.0f);
            *(float4*)(hr + c) = v;
        }
    }
    __syncthreads();

    // ---- build layer-1 A fragments from h0 (warp-local rows) ----
    uint32_t Ahi[8][4], Alo[8][4];
    {
        const float* r0p = h0s + (warp * 16 + g)     * H0S;
        const float* r1p = h0s + (warp * 16 + g + 8) * H0S;
        #pragma unroll
        for (int q = 0; q < 8; q++) {
            int c = 16 * q + 2 * t;
            float2 p0 = *(const float2*)(r0p + c);
            float2 p1 = *(const float2*)(r1p + c);
            float2 p2 = *(const float2*)(r0p + c + 8);
            float2 p3 = *(const float2*)(r1p + c + 8);
            split2(p0.x, p0.y, Ahi[q][0], Alo[q][0]);
            split2(p1.x, p1.y, Ahi[q][1], Alo[q][1]);
            split2(p2.x, p2.y, Ahi[q][2], Alo[q][2]);
            split2(p3.x, p3.y, Ahi[q][3], Alo[q][3]);
        }
    }

    // ---- hidden layers 1 and 2: MMA + in-place epilogue (A overwritten after D done) ----
    #pragma unroll 1
    for (int L = 0; L < 2; L++) {
        float D[16][4];
        #pragma unroll
        for (int j = 0; j < 16; j++) {
            D[j][0] = 0.f; D[j][1] = 0.f; D[j][2] = 0.f; D[j][3] = 0.f;
        }
        layer_mma(D, Ahi, Alo, g_wb + (size_t)L * (8 * 16 * 32), lane);
        const float* bL = (L == 0) ? b1 : b2;
        #pragma unroll
        for (int q = 0; q < 8; q++) {
            int j0 = 2 * q, j1 = 2 * q + 1;
            float2 bj0 = *(const float2*)(bL + j0 * 8 + t * 2);
            float2 bj1 = *(const float2*)(bL + j1 * 8 + t * 2);
            float v0 = fmaxf(D[j0][0] + bj0.x, 0.f);
            float v1 = fmaxf(D[j0][1] + bj0.y, 0.f);
            float v2 = fmaxf(D[j0][2] + bj0.x, 0.f);
            float v3 = fmaxf(D[j0][3] + bj0.y, 0.f);
            split2(v0, v1, Ahi[q][0], Alo[q][0]);
            split2(v2, v3, Ahi[q][1], Alo[q][1]);
            float u0 = fmaxf(D[j1][0] + bj1.x, 0.f);
            float u1 = fmaxf(D[j1][1] + bj1.y, 0.f);
            float u2 = fmaxf(D[j1][2] + bj1.x, 0.f);
            float u3 = fmaxf(D[j1][3] + bj1.y, 0.f);
            split2(u0, u1, Ahi[q][2], Alo[q][2]);
            split2(u2, u3, Ahi[q][3], Alo[q][3]);
        }
    }

    // ---- layer 3 (w3) + fused layer 4 (w4) + scatter ----
    {
        float D[16][4];
        #pragma unroll
        for (int j = 0; j < 16; j++) {
            D[j][0] = 0.f; D[j][1] = 0.f; D[j][2] = 0.f; D[j][3] = 0.f;
        }
        layer_mma(D, Ahi, Alo, g_wb + (size_t)2 * (8 * 16 * 32), lane);

        float m0g = 0.f, m1g = 0.f, m0h = 0.f, m1h = 0.f;
        #pragma unroll
        for (int j = 0; j < 16; j++) {
            float2 bj = *(const float2*)(b3 + j * 8 + t * 2);
            float v0 = fmaxf(D[j][0] + bj.x, 0.f);
            float v1 = fmaxf(D[j][1] + bj.y, 0.f);
            float v2 = fmaxf(D[j][2] + bj.x, 0.f);
            float v3 = fmaxf(D[j][3] + bj.y, 0.f);
            float4 w4v = *(const float4*)(w4 + 2 * (j * 8 + t * 2));  // w4[2k..2k+3]
            m0g = fmaf(v0, w4v.x, fmaf(v1, w4v.z, m0g));
            m1g = fmaf(v0, w4v.y, fmaf(v1, w4v.w, m1g));
            m0h = fmaf(v2, w4v.x, fmaf(v3, w4v.z, m0h));
            m1h = fmaf(v2, w4v.y, fmaf(v3, w4v.w, m1h));
        }
        // reduce across the quad (t = 0..3)
        #pragma unroll
        for (int d = 1; d <= 2; d <<= 1) {
            m0g += __shfl_xor_sync(0xFFFFFFFFu, m0g, d);
            m1g += __shfl_xor_sync(0xFFFFFFFFu, m1g, d);
            m0h += __shfl_xor_sync(0xFFFFFFFFu, m0h, d);
            m1h += __shfl_xor_sync(0xFFFFFFFFu, m1h, d);
        }
        if (t == 0) {
            float bb0 = b4[0], bb1 = b4[1];
            int d0 = sdst[warp * 16 + g];
            if (d0 >= 0) {
                atomicAdd(&out[2 * d0],     m0g + bb0);
                atomicAdd(&out[2 * d0 + 1], m1g + bb1);
            }
            int d1 = sdst[warp * 16 + g + 8];
            if (d1 >= 0) {
                atomicAdd(&out[2 * d1],     m0h + bb0);
                atomicAdd(&out[2 * d1 + 1], m1h + bb1);
            }
        }
    }
}

extern "C" void kernel_launch(void* const* d_in, const int* in_sizes, int n_in,
                              void* d_out, int out_size) {
    const float* pos   = (const float*)d_in[0];
    const float* vel   = (const float*)d_in[1];
    const float* a     = (const float*)d_in[2];
    const float* vnorm = (const float*)d_in[3];
    const float* w0    = (const float*)d_in[4];
    const float* b0    = (const float*)d_in[5];
    const float* w1    = (const float*)d_in[6];
    const float* b1    = (const float*)d_in[7];
    const float* w2    = (const float*)d_in[8];
    const float* b2    = (const float*)d_in[9];
    const float* w3    = (const float*)d_in[10];
    const float* b3    = (const float*)d_in[11];
    const float* w4    = (const float*)d_in[12];
    const float* b4    = (const float*)d_in[13];
    const int*   ei    = (const int*)d_in[14];    // int32 [2, E]
    const int*   did   = (const int*)d_in[15];
    float*       out   = (float*)d_out;

    int E = in_sizes[14] / 2;
    int N = in_sizes[0] / 2;

    cudaFuncSetAttribute(gnn_mma_kernel,
                         cudaFuncAttributeMaxDynamicSharedMemorySize, SMEM_BYTES);

    int prep_n = (out_size > NFRAG) ? out_size : NFRAG;
    prep_kernel<<<(prep_n + 255) / 256, 256>>>(w1, w2, w3, out, out_size);

    int tiles = (E + TILE - 1) / TILE;
    gnn_mma_kernel<<<tiles, NTHREADS, SMEM_BYTES>>>(
        pos, vel, a, vnorm, w0, b0, b1, b2, b3, w4, b4,
        ei, did, out, E, N);
}

// round 7
// speedup vs baseline: 1.4405x; 1.3693x over previous
#include <cuda_runtime.h>
#include <cuda_bf16.h>
#include <math.h>
#include <stdint.h>

#define HID 128
#define TILE 192           // edges per CTA (12 warps x 16)
#define NTHREADS 384
#define IN_SZ 9
#define FST 12             // feats row stride (floats)
#define NFRAG (3 * 8 * 16 * 32)

// Pre-packed weight fragments for w1..w3 (m16n8k16 B-frag):
// g_wb[L][q][nt][lane] = uint4 {bhi_r0, bhi_r1, blo_r0, blo_r1}
// r0 -> k = 16q + 2t + {0,1}, r1 -> k = 16q + 2t + 8 + {0,1}, n = 8nt + g
__device__ uint4 g_wb[NFRAG];
// Layer-0 fragments: K=16 (rows 9..15 zero), 16 n-tiles
__device__ uint4 g_w0[16 * 32];

__device__ __forceinline__ void split2(float v0, float v1, uint32_t& hi, uint32_t& lo) {
    __nv_bfloat16 h0 = __float2bfloat16_rn(v0);
    __nv_bfloat16 h1 = __float2bfloat16_rn(v1);
    float r0 = v0 - __bfloat162float(h0);
    float r1 = v1 - __bfloat162float(h1);
    hi = (uint32_t)__bfloat16_as_ushort(h0) | ((uint32_t)__bfloat16_as_ushort(h1) << 16);
    lo = (uint32_t)__bfloat16_as_ushort(__float2bfloat16_rn(r0))
       | ((uint32_t)__bfloat16_as_ushort(__float2bfloat16_rn(r1)) << 16);
}

__device__ __forceinline__ void mma16816(float* d,
                                         uint32_t a0, uint32_t a1, uint32_t a2, uint32_t a3,
                                         uint32_t b0, uint32_t b1) {
    asm volatile(
        "mma.sync.aligned.m16n8k16.row.col.f32.bf16.bf16.f32 "
        "{%0,%1,%2,%3}, {%4,%5,%6,%7}, {%8,%9}, {%0,%1,%2,%3};"
        : "+f"(d[0]), "+f"(d[1]), "+f"(d[2]), "+f"(d[3])
        : "r"(a0), "r"(a1), "r"(a2), "r"(a3), "r"(b0), "r"(b1));
}

// 3-pass split MMA for one k-chunk q against 8 j-fragments (interleaved).
__device__ __forceinline__ void mma_block(
    float (&D)[16][4], int jb,
    const uint32_t* Ahi, const uint32_t* Alo,
    const uint4* __restrict__ frag_base, int lane)
{
    uint4 B[8];
    #pragma unroll
    for (int j = 0; j < 8; j++) B[j] = frag_base[(jb * 8 + j) * 32 + lane];
    #pragma unroll
    for (int j = 0; j < 8; j++)
        mma16816(D[jb * 8 + j], Ahi[0], Ahi[1], Ahi[2], Ahi[3], B[j].x, B[j].y);
    #pragma unroll
    for (int j = 0; j < 8; j++)
        mma16816(D[jb * 8 + j], Ahi[0], Ahi[1], Ahi[2], Ahi[3], B[j].z, B[j].w);
    #pragma unroll
    for (int j = 0; j < 8; j++)
        mma16816(D[jb * 8 + j], Alo[0], Alo[1], Alo[2], Alo[3], B[j].x, B[j].y);
}

// Epilogue: D + bias, ReLU, split back into A (in place).
__device__ __forceinline__ void epilogue(
    float (&D)[16][4], uint32_t (&Ahi)[8][4], uint32_t (&Alo)[8][4],
    const float* __restrict__ bL, int t)
{
    #pragma unroll
    for (int q = 0; q < 8; q++) {
        int j0 = 2 * q, j1 = 2 * q + 1;
        float2 bj0 = *(const float2*)(bL + j0 * 8 + t * 2);
        float2 bj1 = *(const float2*)(bL + j1 * 8 + t * 2);
        float v0 = fmaxf(D[j0][0] + bj0.x, 0.f);
        float v1 = fmaxf(D[j0][1] + bj0.y, 0.f);
        float v2 = fmaxf(D[j0][2] + bj0.x, 0.f);
        float v3 = fmaxf(D[j0][3] + bj0.y, 0.f);
        split2(v0, v1, Ahi[q][0], Alo[q][0]);
        split2(v2, v3, Ahi[q][1], Alo[q][1]);
        float u0 = fmaxf(D[j1][0] + bj1.x, 0.f);
        float u1 = fmaxf(D[j1][1] + bj1.y, 0.f);
        float u2 = fmaxf(D[j1][2] + bj1.x, 0.f);
        float u3 = fmaxf(D[j1][3] + bj1.y, 0.f);
        split2(u0, u1, Ahi[q][2], Alo[q][2]);
        split2(u2, u3, Ahi[q][3], Alo[q][3]);
    }
}

// ---------------- prep (+ output zeroing; keeps launch count at 2) ----------------
__global__ void prep_kernel(const float* __restrict__ w0,
                            const float* __restrict__ w1,
                            const float* __restrict__ w2,
                            const float* __restrict__ w3,
                            float* __restrict__ out, int out_n) {
    int s = blockIdx.x * blockDim.x + threadIdx.x;
    if (s < out_n) out[s] = 0.0f;
    if (s < 16 * 32) {
        int lane = s & 31;
        int nt   = s >> 5;
        int g = lane >> 2, t = lane & 3;
        int n  = nt * 8 + g;
        int k0 = t * 2;
        float v00 = w0[k0 * HID + n];
        float v01 = w0[(k0 + 1) * HID + n];
        float v10 = (t == 0) ? w0[8 * HID + n] : 0.0f;   // k=8 valid only for t=0
        float v11 = 0.0f;                                 // k=9..15 zero-padded
        uint4 o;
        split2(v00, v01, o.x, o.z);
        split2(v10, v11, o.y, o.w);
        g_w0[s] = o;
    }
    if (s < NFRAG) {
        int lane = s & 31;
        int nt   = (s >> 5) & 15;
        int q    = (s >> 9) & 7;
        int L    = s >> 12;
        int g = lane >> 2, t = lane & 3;
        int n  = nt * 8 + g;
        int k0 = q * 16 + t * 2;
        const float* W = (L == 0) ? w1 : (L == 1) ? w2 : w3;
        float v00 = W[k0 * HID + n];
        float v01 = W[(k0 + 1) * HID + n];
        float v10 = W[(k0 + 8) * HID + n];
        float v11 = W[(k0 + 9) * HID + n];
        uint4 o;
        split2(v00, v01, o.x, o.z);
        split2(v10, v11, o.y, o.w);
        g_wb[s] = o;
    }
}

// ---------------- main kernel ----------------
__global__ __launch_bounds__(NTHREADS, 1)
void gnn_mma_kernel(
    const float* __restrict__ pos,
    const float* __restrict__ vel,
    const float* __restrict__ a,
    const float* __restrict__ vnorm,
    const float* __restrict__ b0,
    const float* __restrict__ b1, const float* __restrict__ b2, const float* __restrict__ b3,
    const float* __restrict__ w4, const float* __restrict__ b4,
    const int* __restrict__ ei,
    const int* __restrict__ data_id_p,
    float* __restrict__ out,
    int E, int N)
{
    __shared__ float feats[TILE * FST];
    __shared__ int   sdst[TILE];

    const int tid  = threadIdx.x;
    const int warp = tid >> 5;
    const int lane = tid & 31;
    const int g = lane >> 2, t = lane & 3;

    // ---- feature build: 1 thread per edge (tid < 192) ----
    if (tid < TILE) {
        int e = blockIdx.x * TILE + tid;
        float* f = feats + tid * FST;
        int dstv = -1;
        if (e < E) {
            dstv    = ei[e];
            int src = ei[E + e];
            float inv_vn = 1.0f / vnorm[0];
            float dpx = (pos[2 * src]     - pos[2 * dstv])     * 10.0f;  // / MAX_RADIUS
            float dpy = (pos[2 * src + 1] - pos[2 * dstv + 1]) * 10.0f;
            f[0] = dpx; f[1] = dpy;
            f[2] = sqrtf(dpx * dpx + dpy * dpy);
            f[3] = vel[2 * dstv]     * inv_vn;
            f[4] = vel[2 * dstv + 1] * inv_vn;
            f[5] = vel[2 * src]      * inv_vn;
            f[6] = vel[2 * src + 1]  * inv_vn;
            int did = *data_id_p;
            const float* emb = a + ((size_t)did * N + dstv) * 2;
            f[7] = emb[0]; f[8] = emb[1];
        } else {
            #pragma unroll
            for (int k = 0; k < IN_SZ; k++) f[k] = 0.0f;
        }
        f[9] = 0.0f;   // zero pad (k=9)
        sdst[tid] = dstv;
    }
    __syncthreads();

    uint32_t Ahi[8][4], Alo[8][4];
    float D[16][4];

    // ---- layer 0 via MMA (K=16, zero-padded) ----
    {
        const float* r0p = feats + (warp * 16 + g)     * FST;
        const float* r1p = feats + (warp * 16 + g + 8) * FST;
        float2 p0 = *(const float2*)(r0p + 2 * t);
        float2 p1 = *(const float2*)(r1p + 2 * t);
        float2 p2 = make_float2(0.f, 0.f), p3 = make_float2(0.f, 0.f);
        if (t == 0) {                       // cols (8,9); t>=1 -> cols >= 10 are zero
            p2 = *(const float2*)(r0p + 8);
            p3 = *(const float2*)(r1p + 8);
        }
        uint32_t a0h, a0l, a1h, a1l, a2h, a2l, a3h, a3l;
        split2(p0.x, p0.y, a0h, a0l);
        split2(p1.x, p1.y, a1h, a1l);
        split2(p2.x, p2.y, a2h, a2l);
        split2(p3.x, p3.y, a3h, a3l);
        uint32_t ah[4] = {a0h, a1h, a2h, a3h};
        uint32_t al[4] = {a0l, a1l, a2l, a3l};
        #pragma unroll
        for (int j = 0; j < 16; j++) {
            D[j][0] = 0.f; D[j][1] = 0.f; D[j][2] = 0.f; D[j][3] = 0.f;
        }
        mma_block(D, 0, ah, al, g_w0, lane);
        mma_block(D, 1, ah, al, g_w0, lane);
        epilogue(D, Ahi, Alo, b0, t);
    }

    // ---- hidden layers 1 and 2 ----
    #pragma unroll 1
    for (int L = 0; L < 2; L++) {
        #pragma unroll
        for (int j = 0; j < 16; j++) {
            D[j][0] = 0.f; D[j][1] = 0.f; D[j][2] = 0.f; D[j][3] = 0.f;
        }
        const uint4* wbL = g_wb + (size_t)L * (8 * 16 * 32);
        #pragma unroll
        for (int q = 0; q < 8; q++) {
            mma_block(D, 0, Ahi[q], Alo[q], wbL + (size_t)q * 16 * 32, lane);
            mma_block(D, 1, Ahi[q], Alo[q], wbL + (size_t)q * 16 * 32, lane);
        }
        epilogue(D, Ahi, Alo, (L == 0) ? b1 : b2, t);
    }

    // ---- layer 3 (w3) + fused layer 4 (w4) + scatter ----
    {
        #pragma unroll
        for (int j = 0; j < 16; j++) {
            D[j][0] = 0.f; D[j][1] = 0.f; D[j][2] = 0.f; D[j][3] = 0.f;
        }
        const uint4* wbL = g_wb + (size_t)2 * (8 * 16 * 32);
        #pragma unroll
        for (int q = 0; q < 8; q++) {
            mma_block(D, 0, Ahi[q], Alo[q], wbL + (size_t)q * 16 * 32, lane);
            mma_block(D, 1, Ahi[q], Alo[q], wbL + (size_t)q * 16 * 32, lane);
        }
        float m0g = 0.f, m1g = 0.f, m0h = 0.f, m1h = 0.f;
        #pragma unroll
        for (int j = 0; j < 16; j++) {
            float2 bj = *(const float2*)(b3 + j * 8 + t * 2);
            float v0 = fmaxf(D[j][0] + bj.x, 0.f);
            float v1 = fmaxf(D[j][1] + bj.y, 0.f);
            float v2 = fmaxf(D[j][2] + bj.x, 0.f);
            float v3 = fmaxf(D[j][3] + bj.y, 0.f);
            float4 w4v = *(const float4*)(w4 + 2 * (j * 8 + t * 2));
            m0g = fmaf(v0, w4v.x, fmaf(v1, w4v.z, m0g));
            m1g = fmaf(v0, w4v.y, fmaf(v1, w4v.w, m1g));
            m0h = fmaf(v2, w4v.x, fmaf(v3, w4v.z, m0h));
            m1h = fmaf(v2, w4v.y, fmaf(v3, w4v.w, m1h));
        }
        #pragma unroll
        for (int d = 1; d <= 2; d <<= 1) {
            m0g += __shfl_xor_sync(0xFFFFFFFFu, m0g, d);
            m1g += __shfl_xor_sync(0xFFFFFFFFu, m1g, d);
            m0h += __shfl_xor_sync(0xFFFFFFFFu, m0h, d);
            m1h += __shfl_xor_sync(0xFFFFFFFFu, m1h, d);
        }
        if (t == 0) {
            float bb0 = b4[0], bb1 = b4[1];
            int d0 = sdst[warp * 16 + g];
            if (d0 >= 0) {
                atomicAdd(&out[2 * d0],     m0g + bb0);
                atomicAdd(&out[2 * d0 + 1], m1g + bb1);
            }
            int d1 = sdst[warp * 16 + g + 8];
            if (d1 >= 0) {
                atomicAdd(&out[2 * d1],     m0h + bb0);
                atomicAdd(&out[2 * d1 + 1], m1h + bb1);
            }
        }
    }
}

extern "C" void kernel_launch(void* const* d_in, const int* in_sizes, int n_in,
                              void* d_out, int out_size) {
    const float* pos   = (const float*)d_in[0];
    const float* vel   = (const float*)d_in[1];
    const float* a     = (const float*)d_in[2];
    const float* vnorm = (const float*)d_in[3];
    const float* w0    = (const float*)d_in[4];
    const float* b0    = (const float*)d_in[5];
    const float* w1    = (const float*)d_in[6];
    const float* b1    = (const float*)d_in[7];
    const float* w2    = (const float*)d_in[8];
    const float* b2    = (const float*)d_in[9];
    const float* w3    = (const float*)d_in[10];
    const float* b3    = (const float*)d_in[11];
    const float* w4    = (const float*)d_in[12];
    const float* b4    = (const float*)d_in[13];
    const int*   ei    = (const int*)d_in[14];    // int32 [2, E]
    const int*   did   = (const int*)d_in[15];
    float*       out   = (float*)d_out;

    int E = in_sizes[14] / 2;
    int N = in_sizes[0] / 2;

    int prep_n = (out_size > NFRAG) ? out_size : NFRAG;
    prep_kernel<<<(prep_n + 255) / 256, 256>>>(w0, w1, w2, w3, out, out_size);

    int tiles = (E + TILE - 1) / TILE;
    gnn_mma_kernel<<<tiles, NTHREADS>>>(
        pos, vel, a, vnorm, b0, b1, b2, b3, w4, b4,
        ei, did, out, E, N);
}

// round 8
// speedup vs baseline: 1.5503x; 1.0762x over previous
#include <cuda_runtime.h>
#include <cuda_bf16.h>
#include <math.h>
#include <stdint.h>

#define HID 128
#define TILE 128           // edges per CTA (8 warps x 16)
#define NTHREADS 256
#define IN_SZ 9
#define FST 12             // feats row stride (floats)
#define NFRAG (3 * 8 * 16 * 32)

// SMEM layout (floats): feats[128*12], sdst[128], then A-fragments:
// Asm[warp][q][hi/lo][lane] as uint4  -> 8*8*2*32 uint4 = 65536 B
#define SM_FEATS_FLOATS (TILE * FST)          // 1536
#define SM_SDST_OFF     SM_FEATS_FLOATS       // int[128]
#define SM_A_OFF_FLOATS (SM_FEATS_FLOATS + TILE)   // 1664 floats = 6656 B (16B aligned)
#define SMEM_BYTES      (SM_A_OFF_FLOATS * 4 + 8 * 8 * 2 * 32 * 16)

// Pre-packed weight fragments for w1..w3 (m16n8k16 B-frag):
// g_wb[L][q][nt][lane] = uint4 {bhi_r0, bhi_r1, blo_r0, blo_r1}
__device__ uint4 g_wb[NFRAG];
// Layer-0 fragments: K=16 (rows 9..15 zero), 16 n-tiles
__device__ uint4 g_w0[16 * 32];

__device__ __forceinline__ void split2(float v0, float v1, uint32_t& hi, uint32_t& lo) {
    __nv_bfloat16 h0 = __float2bfloat16_rn(v0);
    __nv_bfloat16 h1 = __float2bfloat16_rn(v1);
    float r0 = v0 - __bfloat162float(h0);
    float r1 = v1 - __bfloat162float(h1);
    hi = (uint32_t)__bfloat16_as_ushort(h0) | ((uint32_t)__bfloat16_as_ushort(h1) << 16);
    lo = (uint32_t)__bfloat16_as_ushort(__float2bfloat16_rn(r0))
       | ((uint32_t)__bfloat16_as_ushort(__float2bfloat16_rn(r1)) << 16);
}

__device__ __forceinline__ void mma16816(float* d,
                                         uint32_t a0, uint32_t a1, uint32_t a2, uint32_t a3,
                                         uint32_t b0, uint32_t b1) {
    asm volatile(
        "mma.sync.aligned.m16n8k16.row.col.f32.bf16.bf16.f32 "
        "{%0,%1,%2,%3}, {%4,%5,%6,%7}, {%8,%9}, {%0,%1,%2,%3};"
        : "+f"(d[0]), "+f"(d[1]), "+f"(d[2]), "+f"(d[3])
        : "r"(a0), "r"(a1), "r"(a2), "r"(a3), "r"(b0), "r"(b1));
}

// 3-pass split MMA for one k-chunk against 4 j-fragments.
__device__ __forceinline__ void mma_block4(
    float (&D)[16][4], int jb,
    const uint32_t* ah, const uint32_t* al,
    const uint4* __restrict__ frag_base, int lane)
{
    uint4 B[4];
    #pragma unroll
    for (int j = 0; j < 4; j++) B[j] = frag_base[(jb * 4 + j) * 32 + lane];
    #pragma unroll
    for (int j = 0; j < 4; j++)
        mma16816(D[jb * 4 + j], ah[0], ah[1], ah[2], ah[3], B[j].x, B[j].y);
    #pragma unroll
    for (int j = 0; j < 4; j++)
        mma16816(D[jb * 4 + j], ah[0], ah[1], ah[2], ah[3], B[j].z, B[j].w);
    #pragma unroll
    for (int j = 0; j < 4; j++)
        mma16816(D[jb * 4 + j], al[0], al[1], al[2], al[3], B[j].x, B[j].y);
}

// Epilogue: D + bias, ReLU, split, store hi/lo fragment pairs to thread-private smem.
__device__ __forceinline__ void epilogue_sts(
    float (&D)[16][4], uint4* __restrict__ abase, const float* __restrict__ bL,
    int t, int lane)
{
    #pragma unroll
    for (int q = 0; q < 8; q++) {
        int j0 = 2 * q, j1 = 2 * q + 1;
        float2 bj0 = *(const float2*)(bL + j0 * 8 + t * 2);
        float2 bj1 = *(const float2*)(bL + j1 * 8 + t * 2);
        float v0 = fmaxf(D[j0][0] + bj0.x, 0.f);
        float v1 = fmaxf(D[j0][1] + bj0.y, 0.f);
        float v2 = fmaxf(D[j0][2] + bj0.x, 0.f);
        float v3 = fmaxf(D[j0][3] + bj0.y, 0.f);
        float u0 = fmaxf(D[j1][0] + bj1.x, 0.f);
        float u1 = fmaxf(D[j1][1] + bj1.y, 0.f);
        float u2 = fmaxf(D[j1][2] + bj1.x, 0.f);
        float u3 = fmaxf(D[j1][3] + bj1.y, 0.f);
        uint4 hi, lo;
        split2(v0, v1, hi.x, lo.x);
        split2(v2, v3, hi.y, lo.y);
        split2(u0, u1, hi.z, lo.z);
        split2(u2, u3, hi.w, lo.w);
        abase[q * 64 + lane]      = hi;
        abase[q * 64 + 32 + lane] = lo;
    }
}

// ---------------- prep (+ output zeroing; keeps launch count at 2) ----------------
__global__ void prep_kernel(const float* __restrict__ w0,
                            const float* __restrict__ w1,
                            const float* __restrict__ w2,
                            const float* __restrict__ w3,
                            float* __restrict__ out, int out_n) {
    int s = blockIdx.x * blockDim.x + threadIdx.x;
    if (s < out_n) out[s] = 0.0f;
    if (s < 16 * 32) {
        int lane = s & 31;
        int nt   = s >> 5;
        int g = lane >> 2, t = lane & 3;
        int n  = nt * 8 + g;
        int k0 = t * 2;
        float v00 = w0[k0 * HID + n];
        float v01 = w0[(k0 + 1) * HID + n];
        float v10 = (t == 0) ? w0[8 * HID + n] : 0.0f;
        float v11 = 0.0f;
        uint4 o;
        split2(v00, v01, o.x, o.z);
        split2(v10, v11, o.y, o.w);
        g_w0[s] = o;
    }
    if (s < NFRAG) {
        int lane = s & 31;
        int nt   = (s >> 5) & 15;
        int q    = (s >> 9) & 7;
        int L    = s >> 12;
        int g = lane >> 2, t = lane & 3;
        int n  = nt * 8 + g;
        int k0 = q * 16 + t * 2;
        const float* W = (L == 0) ? w1 : (L == 1) ? w2 : w3;
        float v00 = W[k0 * HID + n];
        float v01 = W[(k0 + 1) * HID + n];
        float v10 = W[(k0 + 8) * HID + n];
        float v11 = W[(k0 + 9) * HID + n];
        uint4 o;
        split2(v00, v01, o.x, o.z);
        split2(v10, v11, o.y, o.w);
        g_wb[s] = o;
    }
}

// ---------------- main kernel ----------------
__global__ __launch_bounds__(NTHREADS, 2)
void gnn_mma_kernel(
    const float* __restrict__ pos,
    const float* __restrict__ vel,
    const float* __restrict__ a,
    const float* __restrict__ vnorm,
    const float* __restrict__ b0,
    const float* __restrict__ b1, const float* __restrict__ b2, const float* __restrict__ b3,
    const float* __restrict__ w4, const float* __restrict__ b4,
    const int* __restrict__ ei,
    const int* __restrict__ data_id_p,
    float* __restrict__ out,
    int E, int N)
{
    extern __shared__ float sm[];
    float* feats = sm;                               // [TILE][FST]
    int*   sdst  = (int*)(sm + SM_SDST_OFF);         // [TILE]
    uint4* Asm   = (uint4*)(sm + SM_A_OFF_FLOATS);   // [8 warps][8 q][2][32 lanes]

    const int tid  = threadIdx.x;
    const int warp = tid >> 5;
    const int lane = tid & 31;
    const int g = lane >> 2, t = lane & 3;
    uint4* abase = Asm + warp * 512;

    // ---- feature build: 1 thread per edge ----
    if (tid < TILE) {
        int e = blockIdx.x * TILE + tid;
        float* f = feats + tid * FST;
        int dstv = -1;
        if (e < E) {
            dstv    = ei[e];
            int src = ei[E + e];
            float inv_vn = 1.0f / vnorm[0];
            float dpx = (pos[2 * src]     - pos[2 * dstv])     * 10.0f;  // / MAX_RADIUS
            float dpy = (pos[2 * src + 1] - pos[2 * dstv + 1]) * 10.0f;
            f[0] = dpx; f[1] = dpy;
            f[2] = sqrtf(dpx * dpx + dpy * dpy);
            f[3] = vel[2 * dstv]     * inv_vn;
            f[4] = vel[2 * dstv + 1] * inv_vn;
            f[5] = vel[2 * src]      * inv_vn;
            f[6] = vel[2 * src + 1]  * inv_vn;
            int did = *data_id_p;
            const float* emb = a + ((size_t)did * N + dstv) * 2;
            f[7] = emb[0]; f[8] = emb[1];
        } else {
            #pragma unroll
            for (int k = 0; k < IN_SZ; k++) f[k] = 0.0f;
        }
        f[9] = 0.0f;
        sdst[tid] = dstv;
    }
    __syncthreads();

    float D[16][4];

    // ---- layer 0 via MMA (K=16, zero-padded) ----
    {
        const float* r0p = feats + (warp * 16 + g)     * FST;
        const float* r1p = feats + (warp * 16 + g + 8) * FST;
        float2 p0 = *(const float2*)(r0p + 2 * t);
        float2 p1 = *(const float2*)(r1p + 2 * t);
        float2 p2 = make_float2(0.f, 0.f), p3 = make_float2(0.f, 0.f);
        if (t == 0) {
            p2 = *(const float2*)(r0p + 8);
            p3 = *(const float2*)(r1p + 8);
        }
        uint32_t ah[4], al[4];
        split2(p0.x, p0.y, ah[0], al[0]);
        split2(p1.x, p1.y, ah[1], al[1]);
        split2(p2.x, p2.y, ah[2], al[2]);
        split2(p3.x, p3.y, ah[3], al[3]);
        #pragma unroll
        for (int j = 0; j < 16; j++) {
            D[j][0] = 0.f; D[j][1] = 0.f; D[j][2] = 0.f; D[j][3] = 0.f;
        }
        #pragma unroll
        for (int jb = 0; jb < 4; jb++) mma_block4(D, jb, ah, al, g_w0, lane);
        epilogue_sts(D, abase, b0, t, lane);
    }

    // ---- hidden layers 1 and 2 (A in thread-private smem) ----
    #pragma unroll 1
    for (int L = 0; L < 2; L++) {
        #pragma unroll
        for (int j = 0; j < 16; j++) {
            D[j][0] = 0.f; D[j][1] = 0.f; D[j][2] = 0.f; D[j][3] = 0.f;
        }
        const uint4* wbL = g_wb + (size_t)L * (8 * 16 * 32);
        #pragma unroll
        for (int q = 0; q < 8; q++) {
            uint4 h4 = abase[q * 64 + lane];
            uint4 l4 = abase[q * 64 + 32 + lane];
            uint32_t ah[4] = {h4.x, h4.y, h4.z, h4.w};
            uint32_t al[4] = {l4.x, l4.y, l4.z, l4.w};
            const uint4* fb = wbL + (size_t)q * 16 * 32;
            #pragma unroll
            for (int jb = 0; jb < 4; jb++) mma_block4(D, jb, ah, al, fb, lane);
        }
        epilogue_sts(D, abase, (L == 0) ? b1 : b2, t, lane);
    }

    // ---- layer 3 (w3) + fused layer 4 (w4) + scatter ----
    {
        #pragma unroll
        for (int j = 0; j < 16; j++) {
            D[j][0] = 0.f; D[j][1] = 0.f; D[j][2] = 0.f; D[j][3] = 0.f;
        }
        const uint4* wbL = g_wb + (size_t)2 * (8 * 16 * 32);
        #pragma unroll
        for (int q = 0; q < 8; q++) {
            uint4 h4 = abase[q * 64 + lane];
            uint4 l4 = abase[q * 64 + 32 + lane];
            uint32_t ah[4] = {h4.x, h4.y, h4.z, h4.w};
            uint32_t al[4] = {l4.x, l4.y, l4.z, l4.w};
            const uint4* fb = wbL + (size_t)q * 16 * 32;
            #pragma unroll
            for (int jb = 0; jb < 4; jb++) mma_block4(D, jb, ah, al, fb, lane);
        }
        float m0g = 0.f, m1g = 0.f, m0h = 0.f, m1h = 0.f;
        #pragma unroll
        for (int j = 0; j < 16; j++) {
            float2 bj = *(const float2*)(b3 + j * 8 + t * 2);
            float v0 = fmaxf(D[j][0] + bj.x, 0.f);
            float v1 = fmaxf(D[j][1] + bj.y, 0.f);
            float v2 = fmaxf(D[j][2] + bj.x, 0.f);
            float v3 = fmaxf(D[j][3] + bj.y, 0.f);
            float4 w4v = *(const float4*)(w4 + 2 * (j * 8 + t * 2));
            m0g = fmaf(v0, w4v.x, fmaf(v1, w4v.z, m0g));
            m1g = fmaf(v0, w4v.y, fmaf(v1, w4v.w, m1g));
            m0h = fmaf(v2, w4v.x, fmaf(v3, w4v.z, m0h));
            m1h = fmaf(v2, w4v.y, fmaf(v3, w4v.w, m1h));
        }
        #pragma unroll
        for (int d = 1; d <= 2; d <<= 1) {
            m0g += __shfl_xor_sync(0xFFFFFFFFu, m0g, d);
            m1g += __shfl_xor_sync(0xFFFFFFFFu, m1g, d);
            m0h += __shfl_xor_sync(0xFFFFFFFFu, m0h, d);
            m1h += __shfl_xor_sync(0xFFFFFFFFu, m1h, d);
        }
        if (t == 0) {
            float bb0 = b4[0], bb1 = b4[1];
            int d0 = sdst[warp * 16 + g];
            if (d0 >= 0) {
                atomicAdd(&out[2 * d0],     m0g + bb0);
                atomicAdd(&out[2 * d0 + 1], m1g + bb1);
            }
            int d1 = sdst[warp * 16 + g + 8];
            if (d1 >= 0) {
                atomicAdd(&out[2 * d1],     m0h + bb0);
                atomicAdd(&out[2 * d1 + 1], m1h + bb1);
            }
        }
    }
}

extern "C" void kernel_launch(void* const* d_in, const int* in_sizes, int n_in,
                              void* d_out, int out_size) {
    const float* pos   = (const float*)d_in[0];
    const float* vel   = (const float*)d_in[1];
    const float* a     = (const float*)d_in[2];
    const float* vnorm = (const float*)d_in[3];
    const float* w0    = (const float*)d_in[4];
    const float* b0    = (const float*)d_in[5];
    const float* w1    = (const float*)d_in[6];
    const float* b1    = (const float*)d_in[7];
    const float* w2    = (const float*)d_in[8];
    const float* b2    = (const float*)d_in[9];
    const float* w3    = (const float*)d_in[10];
    const float* b3    = (const float*)d_in[11];
    const float* w4    = (const float*)d_in[12];
    const float* b4    = (const float*)d_in[13];
    const int*   ei    = (const int*)d_in[14];    // int32 [2, E]
    const int*   did   = (const int*)d_in[15];
    float*       out   = (float*)d_out;

    int E = in_sizes[14] / 2;
    int N = in_sizes[0] / 2;

    cudaFuncSetAttribute(gnn_mma_kernel,
                         cudaFuncAttributeMaxDynamicSharedMemorySize, SMEM_BYTES);

    int prep_n = (out_size > NFRAG) ? out_size : NFRAG;
    prep_kernel<<<(prep_n + 255) / 256, 256>>>(w0, w1, w2, w3, out, out_size);

    int tiles = (E + TILE - 1) / TILE;
    gnn_mma_kernel<<<tiles, NTHREADS, SMEM_BYTES>>>(
        pos, vel, a, vnorm, b0, b1, b2, b3, w4, b4,
        ei, did, out, E, N);
}

// round 9
// speedup vs baseline: 1.8290x; 1.1798x over previous
#include <cuda_runtime.h>
#include <cuda_bf16.h>
#include <math.h>
#include <stdint.h>

#define HID 128
#define TILE 64            // edges per CTA: 2 groups x 32 edges
#define NTHREADS 128       // 4 warps: pair {0,1} -> group 0, pair {2,3} -> group 1
#define IN_SZ 9
#define FST 12
#define NFRAG (3 * 8 * 16 * 32)

// Pre-packed weight fragments for w1..w3 (m16n8k16 B-frag):
// g_wb[L][q][nt][lane] = uint4 {bhi_r0, bhi_r1, blo_r0, blo_r1}
__device__ uint4 g_wb[NFRAG];
// Layer-0 fragments: K=16 (rows 9..15 zero), 16 n-tiles
__device__ uint4 g_w0[16 * 32];

__device__ __forceinline__ void split2(float v0, float v1, uint32_t& hi, uint32_t& lo) {
    __nv_bfloat16 h0 = __float2bfloat16_rn(v0);
    __nv_bfloat16 h1 = __float2bfloat16_rn(v1);
    float r0 = v0 - __bfloat162float(h0);
    float r1 = v1 - __bfloat162float(h1);
    hi = (uint32_t)__bfloat16_as_ushort(h0) | ((uint32_t)__bfloat16_as_ushort(h1) << 16);
    lo = (uint32_t)__bfloat16_as_ushort(__float2bfloat16_rn(r0))
       | ((uint32_t)__bfloat16_as_ushort(__float2bfloat16_rn(r1)) << 16);
}

__device__ __forceinline__ void mma16816(float* d,
                                         uint32_t a0, uint32_t a1, uint32_t a2, uint32_t a3,
                                         uint32_t b0, uint32_t b1) {
    asm volatile(
        "mma.sync.aligned.m16n8k16.row.col.f32.bf16.bf16.f32 "
        "{%0,%1,%2,%3}, {%4,%5,%6,%7}, {%8,%9}, {%0,%1,%2,%3};"
        : "+f"(d[0]), "+f"(d[1]), "+f"(d[2]), "+f"(d[3])
        : "r"(a0), "r"(a1), "r"(a2), "r"(a3), "r"(b0), "r"(b1));
}

// 3-pass split MMA: one k-chunk, 4 j-fragments, TWO M-tiles sharing B.
__device__ __forceinline__ void mma_block2m(
    float (&D)[2][8][4], int jb,
    const uint4& h0, const uint4& l0, const uint4& h1, const uint4& l1,
    const uint4* __restrict__ frag_base, int lane)
{
    uint4 B[4];
    #pragma unroll
    for (int j = 0; j < 4; j++) B[j] = frag_base[(jb * 4 + j) * 32 + lane];
    #pragma unroll
    for (int j = 0; j < 4; j++)
        mma16816(D[0][jb * 4 + j], h0.x, h0.y, h0.z, h0.w, B[j].x, B[j].y);
    #pragma unroll
    for (int j = 0; j < 4; j++)
        mma16816(D[1][jb * 4 + j], h1.x, h1.y, h1.z, h1.w, B[j].x, B[j].y);
    #pragma unroll
    for (int j = 0; j < 4; j++)
        mma16816(D[0][jb * 4 + j], h0.x, h0.y, h0.z, h0.w, B[j].z, B[j].w);
    #pragma unroll
    for (int j = 0; j < 4; j++)
        mma16816(D[1][jb * 4 + j], h1.x, h1.y, h1.z, h1.w, B[j].z, B[j].w);
    #pragma unroll
    for (int j = 0; j < 4; j++)
        mma16816(D[0][jb * 4 + j], l0.x, l0.y, l0.z, l0.w, B[j].x, B[j].y);
    #pragma unroll
    for (int j = 0; j < 4; j++)
        mma16816(D[1][jb * 4 + j], l1.x, l1.y, l1.z, l1.w, B[j].x, B[j].y);
}

// Epilogue: bias+ReLU+split, write this warp's 4 chunks (both tiles) to group A smem.
__device__ __forceinline__ void epilogue_sts(
    float (&D)[2][8][4], uint4* __restrict__ Ag, const float* __restrict__ bL,
    int nh, int t, int lane)
{
    #pragma unroll
    for (int qq = 0; qq < 4; qq++) {
        int qp = nh * 4 + qq;
        int j0 = 2 * qq, j1 = 2 * qq + 1;
        float2 bj0 = *(const float2*)(bL + (nh * 8 + j0) * 8 + t * 2);
        float2 bj1 = *(const float2*)(bL + (nh * 8 + j1) * 8 + t * 2);
        #pragma unroll
        for (int m = 0; m < 2; m++) {
            float v0 = fmaxf(D[m][j0][0] + bj0.x, 0.f);
            float v1 = fmaxf(D[m][j0][1] + bj0.y, 0.f);
            float v2 = fmaxf(D[m][j0][2] + bj0.x, 0.f);
            float v3 = fmaxf(D[m][j0][3] + bj0.y, 0.f);
            float u0 = fmaxf(D[m][j1][0] + bj1.x, 0.f);
            float u1 = fmaxf(D[m][j1][1] + bj1.y, 0.f);
            float u2 = fmaxf(D[m][j1][2] + bj1.x, 0.f);
            float u3 = fmaxf(D[m][j1][3] + bj1.y, 0.f);
            uint4 hi, lo;
            split2(v0, v1, hi.x, lo.x);
            split2(v2, v3, hi.y, lo.y);
            split2(u0, u1, hi.z, lo.z);
            split2(u2, u3, hi.w, lo.w);
            uint4* p = Ag + ((qp * 2 + m) * 2) * 32;
            p[lane]      = hi;
            p[32 + lane] = lo;
        }
    }
}

// ---------------- prep (+ output zeroing; keeps launch count at 2) ----------------
__global__ void prep_kernel(const float* __restrict__ w0,
                            const float* __restrict__ w1,
                            const float* __restrict__ w2,
                            const float* __restrict__ w3,
                            float* __restrict__ out, int out_n) {
    int s = blockIdx.x * blockDim.x + threadIdx.x;
    if (s < out_n) out[s] = 0.0f;
    if (s < 16 * 32) {
        int lane = s & 31;
        int nt   = s >> 5;
        int g = lane >> 2, t = lane & 3;
        int n  = nt * 8 + g;
        int k0 = t * 2;
        float v00 = w0[k0 * HID + n];
        float v01 = w0[(k0 + 1) * HID + n];
        float v10 = (t == 0) ? w0[8 * HID + n] : 0.0f;
        float v11 = 0.0f;
        uint4 o;
        split2(v00, v01, o.x, o.z);
        split2(v10, v11, o.y, o.w);
        g_w0[s] = o;
    }
    if (s < NFRAG) {
        int lane = s & 31;
        int nt   = (s >> 5) & 15;
        int q    = (s >> 9) & 7;
        int L    = s >> 12;
        int g = lane >> 2, t = lane & 3;
        int n  = nt * 8 + g;
        int k0 = q * 16 + t * 2;
        const float* W = (L == 0) ? w1 : (L == 1) ? w2 : w3;
        float v00 = W[k0 * HID + n];
        float v01 = W[(k0 + 1) * HID + n];
        float v10 = W[(k0 + 8) * HID + n];
        float v11 = W[(k0 + 9) * HID + n];
        uint4 o;
        split2(v00, v01, o.x, o.z);
        split2(v10, v11, o.y, o.w);
        g_wb[s] = o;
    }
}

// ---------------- main kernel ----------------
__global__ __launch_bounds__(NTHREADS, 4)
void gnn_mma_kernel(
    const float* __restrict__ pos,
    const float* __restrict__ vel,
    const float* __restrict__ a,
    const float* __restrict__ vnorm,
    const float* __restrict__ b0,
    const float* __restrict__ b1, const float* __restrict__ b2, const float* __restrict__ b3,
    const float* __restrict__ w4, const float* __restrict__ b4,
    const int* __restrict__ ei,
    const int* __restrict__ data_id_p,
    float* __restrict__ out,
    int E, int N)
{
    __shared__ float feats[TILE * FST];
    __shared__ int   sdst[TILE];
    // A fragments: [group(2)][q(8)][m(2)][hi/lo(2)][lane(32)] uint4 = 32 KB
    __shared__ uint4 Asm[2 * 8 * 2 * 2 * 32];

    const int tid  = threadIdx.x;
    const int warp = tid >> 5;
    const int lane = tid & 31;
    const int g = lane >> 2, t = lane & 3;
    const int g2 = warp >> 1;      // group (32 edges)
    const int nh = warp & 1;       // n-half owned by this warp
    uint4* Ag = Asm + g2 * (8 * 2 * 2 * 32);

    // ---- feature build: 1 thread per edge (tid < 64) ----
    if (tid < TILE) {
        int e = blockIdx.x * TILE + tid;
        float* f = feats + tid * FST;
        int dstv = -1;
        if (e < E) {
            dstv    = ei[e];
            int src = ei[E + e];
            float inv_vn = 1.0f / vnorm[0];
            float dpx = (pos[2 * src]     - pos[2 * dstv])     * 10.0f;  // / MAX_RADIUS
            float dpy = (pos[2 * src + 1] - pos[2 * dstv + 1]) * 10.0f;
            f[0] = dpx; f[1] = dpy;
            f[2] = sqrtf(dpx * dpx + dpy * dpy);
            f[3] = vel[2 * dstv]     * inv_vn;
            f[4] = vel[2 * dstv + 1] * inv_vn;
            f[5] = vel[2 * src]      * inv_vn;
            f[6] = vel[2 * src + 1]  * inv_vn;
            int did = *data_id_p;
            const float* emb = a + ((size_t)did * N + dstv) * 2;
            f[7] = emb[0]; f[8] = emb[1];
        } else {
            #pragma unroll
            for (int k = 0; k < IN_SZ; k++) f[k] = 0.0f;
        }
        f[9] = 0.0f;
        sdst[tid] = dstv;
    }
    __syncthreads();

    float D[2][8][4];

    // ---- layer 0 via MMA (K=16, zero-padded), pair-split over n ----
    {
        uint4 h[2], l[2];
        #pragma unroll
        for (int m = 0; m < 2; m++) {
            const float* r0p = feats + (g2 * 32 + m * 16 + g)     * FST;
            const float* r1p = feats + (g2 * 32 + m * 16 + g + 8) * FST;
            float2 p0 = *(const float2*)(r0p + 2 * t);
            float2 p1 = *(const float2*)(r1p + 2 * t);
            float2 p2 = make_float2(0.f, 0.f), p3 = make_float2(0.f, 0.f);
            if (t == 0) {
                p2 = *(const float2*)(r0p + 8);
                p3 = *(const float2*)(r1p + 8);
            }
            split2(p0.x, p0.y, h[m].x, l[m].x);
            split2(p1.x, p1.y, h[m].y, l[m].y);
            split2(p2.x, p2.y, h[m].z, l[m].z);
            split2(p3.x, p3.y, h[m].w, l[m].w);
        }
        #pragma unroll
        for (int m = 0; m < 2; m++)
            #pragma unroll
            for (int j = 0; j < 8; j++) {
                D[m][j][0] = 0.f; D[m][j][1] = 0.f; D[m][j][2] = 0.f; D[m][j][3] = 0.f;
            }
        const uint4* fb = g_w0 + (size_t)(nh * 8) * 32;
        #pragma unroll
        for (int jb = 0; jb < 2; jb++)
            mma_block2m(D, jb, h[0], l[0], h[1], l[1], fb, lane);
        epilogue_sts(D, Ag, b0, nh, t, lane);
    }
    __syncthreads();

    // ---- hidden layers 1 and 2 ----
    #pragma unroll 1
    for (int L = 0; L < 2; L++) {
        #pragma unroll
        for (int m = 0; m < 2; m++)
            #pragma unroll
            for (int j = 0; j < 8; j++) {
                D[m][j][0] = 0.f; D[m][j][1] = 0.f; D[m][j][2] = 0.f; D[m][j][3] = 0.f;
            }
        const uint4* wbL = g_wb + (size_t)L * (8 * 16 * 32) + (size_t)(nh * 8) * 32;
        #pragma unroll
        for (int q = 0; q < 8; q++) {
            const uint4* ap = Ag + (q * 2) * 2 * 32;
            uint4 h0 = ap[lane];
            uint4 l0 = ap[32 + lane];
            uint4 h1 = ap[64 + lane];
            uint4 l1 = ap[96 + lane];
            const uint4* fb = wbL + (size_t)q * 16 * 32;
            #pragma unroll
            for (int jb = 0; jb < 2; jb++)
                mma_block2m(D, jb, h0, l0, h1, l1, fb, lane);
        }
        __syncthreads();   // all A reads done before overwrite
        epilogue_sts(D, Ag, (L == 0) ? b1 : b2, nh, t, lane);
        __syncthreads();   // writes visible to partner warp
    }

    // ---- layer 3 (w3) + fused layer 4 (w4, partial over this warp's n-half) ----
    {
        #pragma unroll
        for (int m = 0; m < 2; m++)
            #pragma unroll
            for (int j = 0; j < 8; j++) {
                D[m][j][0] = 0.f; D[m][j][1] = 0.f; D[m][j][2] = 0.f; D[m][j][3] = 0.f;
            }
        const uint4* wbL = g_wb + (size_t)2 * (8 * 16 * 32) + (size_t)(nh * 8) * 32;
        #pragma unroll
        for (int q = 0; q < 8; q++) {
            const uint4* ap = Ag + (q * 2) * 2 * 32;
            uint4 h0 = ap[lane];
            uint4 l0 = ap[32 + lane];
            uint4 h1 = ap[64 + lane];
            uint4 l1 = ap[96 + lane];
            const uint4* fb = wbL + (size_t)q * 16 * 32;
            #pragma unroll
            for (int jb = 0; jb < 2; jb++)
                mma_block2m(D, jb, h0, l0, h1, l1, fb, lane);
        }

        float m0g[2] = {0.f, 0.f}, m1g[2] = {0.f, 0.f};
        float m0h[2] = {0.f, 0.f}, m1h[2] = {0.f, 0.f};
        #pragma unroll
        for (int j = 0; j < 8; j++) {
            int n0 = (nh * 8 + j) * 8 + t * 2;
            float2 bj = *(const float2*)(b3 + n0);
            float4 w4v = *(const float4*)(w4 + 2 * n0);
            #pragma unroll
            for (int m = 0; m < 2; m++) {
                float v0 = fmaxf(D[m][j][0] + bj.x, 0.f);
                float v1 = fmaxf(D[m][j][1] + bj.y, 0.f);
                float v2 = fmaxf(D[m][j][2] + bj.x, 0.f);
                float v3 = fmaxf(D[m][j][3] + bj.y, 0.f);
                m0g[m] = fmaf(v0, w4v.x, fmaf(v1, w4v.z, m0g[m]));
                m1g[m] = fmaf(v0, w4v.y, fmaf(v1, w4v.w, m1g[m]));
                m0h[m] = fmaf(v2, w4v.x, fmaf(v3, w4v.z, m0h[m]));
                m1h[m] = fmaf(v2, w4v.y, fmaf(v3, w4v.w, m1h[m]));
            }
        }
        #pragma unroll
        for (int d = 1; d <= 2; d <<= 1) {
            #pragma unroll
            for (int m = 0; m < 2; m++) {
                m0g[m] += __shfl_xor_sync(0xFFFFFFFFu, m0g[m], d);
                m1g[m] += __shfl_xor_sync(0xFFFFFFFFu, m1g[m], d);
                m0h[m] += __shfl_xor_sync(0xFFFFFFFFu, m0h[m], d);
                m1h[m] += __shfl_xor_sync(0xFFFFFFFFu, m1h[m], d);
            }
        }
        if (t == 0) {
            // bias added once (by the nh==0 warp of each pair)
            float bb0 = (nh == 0) ? b4[0] : 0.f;
            float bb1 = (nh == 0) ? b4[1] : 0.f;
            #pragma unroll
            for (int m = 0; m < 2; m++) {
                int d0 = sdst[g2 * 32 + m * 16 + g];
                if (d0 >= 0) {
                    atomicAdd(&out[2 * d0],     m0g[m] + bb0);
                    atomicAdd(&out[2 * d0 + 1], m1g[m] + bb1);
                }
                int d1 = sdst[g2 * 32 + m * 16 + g + 8];
                if (d1 >= 0) {
                    atomicAdd(&out[2 * d1],     m0h[m] + bb0);
                    atomicAdd(&out[2 * d1 + 1], m1h[m] + bb1);
                }
            }
        }
    }
}

extern "C" void kernel_launch(void* const* d_in, const int* in_sizes, int n_in,
                              void* d_out, int out_size) {
    const float* pos   = (const float*)d_in[0];
    const float* vel   = (const float*)d_in[1];
    const float* a     = (const float*)d_in[2];
    const float* vnorm = (const float*)d_in[3];
    const float* w0    = (const float*)d_in[4];
    const float* b0    = (const float*)d_in[5];
    const float* w1    = (const float*)d_in[6];
    const float* b1    = (const float*)d_in[7];
    const float* w2    = (const float*)d_in[8];
    const float* b2    = (const float*)d_in[9];
    const float* w3    = (const float*)d_in[10];
    const float* b3    = (const float*)d_in[11];
    const float* w4    = (const float*)d_in[12];
    const float* b4    = (const float*)d_in[13];
    const int*   ei    = (const int*)d_in[14];    // int32 [2, E]
    const int*   did   = (const int*)d_in[15];
    float*       out   = (float*)d_out;

    int E = in_sizes[14] / 2;
    int N = in_sizes[0] / 2;

    int prep_n = (out_size > NFRAG) ? out_size : NFRAG;
    prep_kernel<<<(prep_n + 255) / 256, 256>>>(w0, w1, w2, w3, out, out_size);

    int tiles = (E + TILE - 1) / TILE;
    gnn_mma_kernel<<<tiles, NTHREADS>>>(
        pos, vel, a, vnorm, b0, b1, b2, b3, w4, b4,
        ei, did, out, E, N);
}

// round 11
// speedup vs baseline: 1.8352x; 1.0034x over previous
#include <cuda_runtime.h>
#include <cuda_bf16.h>
#include <math.h>
#include <stdint.h>

#define HID 128
#define TILE 64            // edges per CTA: ONE group of 64, 4-warp cooperative
#define NTHREADS 128       // warp w owns n-quarter w
#define IN_SZ 9
#define FST 12
#define NFRAG (3 * 8 * 16 * 32)

// Pre-packed weight fragments for w1..w3 (m16n8k16 B-frag):
// g_wb[L][q][nt][lane] = uint4 {bhi_r0, bhi_r1, blo_r0, blo_r1}
__device__ uint4 g_wb[NFRAG];
// Layer-0 fragments: K=16 (rows 9..15 zero), 16 n-tiles
__device__ uint4 g_w0[16 * 32];

__device__ __forceinline__ void split2(float v0, float v1, uint32_t& hi, uint32_t& lo) {
    __nv_bfloat16 h0 = __float2bfloat16_rn(v0);
    __nv_bfloat16 h1 = __float2bfloat16_rn(v1);
    float r0 = v0 - __bfloat162float(h0);
    float r1 = v1 - __bfloat162float(h1);
    hi = (uint32_t)__bfloat16_as_ushort(h0) | ((uint32_t)__bfloat16_as_ushort(h1) << 16);
    lo = (uint32_t)__bfloat16_as_ushort(__float2bfloat16_rn(r0))
       | ((uint32_t)__bfloat16_as_ushort(__float2bfloat16_rn(r1)) << 16);
}

__device__ __forceinline__ void mma16816(float* d,
                                         uint32_t a0, uint32_t a1, uint32_t a2, uint32_t a3,
                                         uint32_t b0, uint32_t b1) {
    asm volatile(
        "mma.sync.aligned.m16n8k16.row.col.f32.bf16.bf16.f32 "
        "{%0,%1,%2,%3}, {%4,%5,%6,%7}, {%8,%9}, {%0,%1,%2,%3};"
        : "+f"(d[0]), "+f"(d[1]), "+f"(d[2]), "+f"(d[3])
        : "r"(a0), "r"(a1), "r"(a2), "r"(a3), "r"(b0), "r"(b1));
}

// 3-pass split MMA for one m-tile against 4 B fragments (this warp's n-quarter).
__device__ __forceinline__ void mma_m(
    float (&Dm)[4][4], const uint4& h, const uint4& l, const uint4 (&B)[4])
{
    #pragma unroll
    for (int j = 0; j < 4; j++)
        mma16816(Dm[j], h.x, h.y, h.z, h.w, B[j].x, B[j].y);
    #pragma unroll
    for (int j = 0; j < 4; j++)
        mma16816(Dm[j], h.x, h.y, h.z, h.w, B[j].z, B[j].w);
    #pragma unroll
    for (int j = 0; j < 4; j++)
        mma16816(Dm[j], l.x, l.y, l.z, l.w, B[j].x, B[j].y);
}

// Epilogue: bias+ReLU+split; this warp's 4 nt cover chunks q' = 2nh+{0,1} for all 4 m.
__device__ __forceinline__ void epilogue_sts(
    float (&D)[4][4][4], uint4* __restrict__ Asm, const float* __restrict__ bL,
    int nh, int t, int lane)
{
    #pragma unroll
    for (int p = 0; p < 2; p++) {
        int qp = 2 * nh + p;
        int j0 = 2 * p, j1 = 2 * p + 1;
        float2 bj0 = *(const float2*)(bL + (nh * 4 + j0) * 8 + t * 2);
        float2 bj1 = *(const float2*)(bL + (nh * 4 + j1) * 8 + t * 2);
        #pragma unroll
        for (int m = 0; m < 4; m++) {
            float v0 = fmaxf(D[m][j0][0] + bj0.x, 0.f);
            float v1 = fmaxf(D[m][j0][1] + bj0.y, 0.f);
            float v2 = fmaxf(D[m][j0][2] + bj0.x, 0.f);
            float v3 = fmaxf(D[m][j0][3] + bj0.y, 0.f);
            float u0 = fmaxf(D[m][j1][0] + bj1.x, 0.f);
            float u1 = fmaxf(D[m][j1][1] + bj1.y, 0.f);
            float u2 = fmaxf(D[m][j1][2] + bj1.x, 0.f);
            float u3 = fmaxf(D[m][j1][3] + bj1.y, 0.f);
            uint4 hi, lo;
            split2(v0, v1, hi.x, lo.x);
            split2(v2, v3, hi.y, lo.y);
            split2(u0, u1, hi.z, lo.z);
            split2(u2, u3, hi.w, lo.w);
            uint4* pp = Asm + ((qp * 4 + m) * 2) * 32;
            pp[lane]      = hi;
            pp[32 + lane] = lo;
        }
    }
}

// ---------------- prep (+ output zeroing; keeps launch count at 2) ----------------
__global__ void prep_kernel(const float* __restrict__ w0,
                            const float* __restrict__ w1,
                            const float* __restrict__ w2,
                            const float* __restrict__ w3,
                            float* __restrict__ out, int out_n) {
    int s = blockIdx.x * blockDim.x + threadIdx.x;
    if (s < out_n) out[s] = 0.0f;
    if (s < 16 * 32) {
        int lane = s & 31;
        int nt   = s >> 5;
        int g = lane >> 2, t = lane & 3;
        int n  = nt * 8 + g;
        int k0 = t * 2;
        float v00 = w0[k0 * HID + n];
        float v01 = w0[(k0 + 1) * HID + n];
        float v10 = (t == 0) ? w0[8 * HID + n] : 0.0f;
        float v11 = 0.0f;
        uint4 o;
        split2(v00, v01, o.x, o.z);
        split2(v10, v11, o.y, o.w);
        g_w0[s] = o;
    }
    if (s < NFRAG) {
        int lane = s & 31;
        int nt   = (s >> 5) & 15;
        int q    = (s >> 9) & 7;
        int L    = s >> 12;
        int g = lane >> 2, t = lane & 3;
        int n  = nt * 8 + g;
        int k0 = q * 16 + t * 2;
        const float* W = (L == 0) ? w1 : (L == 1) ? w2 : w3;
        float v00 = W[k0 * HID + n];
        float v01 = W[(k0 + 1) * HID + n];
        float v10 = W[(k0 + 8) * HID + n];
        float v11 = W[(k0 + 9) * HID + n];
        uint4 o;
        split2(v00, v01, o.x, o.z);
        split2(v10, v11, o.y, o.w);
        g_wb[s] = o;
    }
}

// ---------------- main kernel ----------------
__global__ __launch_bounds__(NTHREADS, 4)
void gnn_mma_kernel(
    const float* __restrict__ pos,
    const float* __restrict__ vel,
    const float* __restrict__ a,
    const float* __restrict__ vnorm,
    const float* __restrict__ b0,
    const float* __restrict__ b1, const float* __restrict__ b2, const float* __restrict__ b3,
    const float* __restrict__ w4, const float* __restrict__ b4,
    const int* __restrict__ ei,
    const int* __restrict__ data_id_p,
    float* __restrict__ out,
    int E, int N)
{
    __shared__ float feats[TILE * FST];
    __shared__ int   sdst[TILE];
    // A fragments: [q(8)][m(4)][hi/lo(2)][lane(32)] uint4 = 32 KB
    __shared__ uint4 Asm[8 * 4 * 2 * 32];

    const int tid  = threadIdx.x;
    const int nh   = tid >> 5;        // warp = n-quarter
    const int lane = tid & 31;
    const int g = lane >> 2, t = lane & 3;

    // ---- feature build: 1 thread per edge (tid < 64) ----
    if (tid < TILE) {
        int e = blockIdx.x * TILE + tid;
        float* f = feats + tid * FST;
        int dstv = -1;
        if (e < E) {
            dstv    = ei[e];
            int src = ei[E + e];
            float inv_vn = 1.0f / vnorm[0];
            float dpx = (pos[2 * src]     - pos[2 * dstv])     * 10.0f;  // / MAX_RADIUS
            float dpy = (pos[2 * src + 1] - pos[2 * dstv + 1]) * 10.0f;
            f[0] = dpx; f[1] = dpy;
            f[2] = sqrtf(dpx * dpx + dpy * dpy);
            f[3] = vel[2 * dstv]     * inv_vn;
            f[4] = vel[2 * dstv + 1] * inv_vn;
            f[5] = vel[2 * src]      * inv_vn;
            f[6] = vel[2 * src + 1]  * inv_vn;
            int did = *data_id_p;
            const float* emb = a + ((size_t)did * N + dstv) * 2;
            f[7] = emb[0]; f[8] = emb[1];
        } else {
            #pragma unroll
            for (int k = 0; k < IN_SZ; k++) f[k] = 0.0f;
        }
        f[9] = 0.0f;
        sdst[tid] = dstv;
    }
    __syncthreads();

    float D[4][4][4];

    // ---- layer 0 via MMA (K=16, zero-padded), n-quarter per warp ----
    {
        #pragma unroll
        for (int m = 0; m < 4; m++)
            #pragma unroll
            for (int j = 0; j < 4; j++) {
                D[m][j][0] = 0.f; D[m][j][1] = 0.f; D[m][j][2] = 0.f; D[m][j][3] = 0.f;
            }
        uint4 B[4];
        #pragma unroll
        for (int j = 0; j < 4; j++) B[j] = g_w0[(nh * 4 + j) * 32 + lane];
        #pragma unroll
        for (int m = 0; m < 4; m++) {
            const float* r0p = feats + (m * 16 + g)     * FST;
            const float* r1p = feats + (m * 16 + g + 8) * FST;
            float2 p0 = *(const float2*)(r0p + 2 * t);
            float2 p1 = *(const float2*)(r1p + 2 * t);
            float2 p2 = make_float2(0.f, 0.f), p3 = make_float2(0.f, 0.f);
            if (t == 0) {
                p2 = *(const float2*)(r0p + 8);
                p3 = *(const float2*)(r1p + 8);
            }
            uint4 h, l;
            split2(p0.x, p0.y, h.x, l.x);
            split2(p1.x, p1.y, h.y, l.y);
            split2(p2.x, p2.y, h.z, l.z);
            split2(p3.x, p3.y, h.w, l.w);
            mma_m(D[m], h, l, B);
        }
        epilogue_sts(D, Asm, b0, nh, t, lane);
    }
    __syncthreads();

    // ---- hidden layers 1 and 2 ----
    #pragma unroll 1
    for (int L = 0; L < 2; L++) {
        #pragma unroll
        for (int m = 0; m < 4; m++)
            #pragma unroll
            for (int j = 0; j < 4; j++) {
                D[m][j][0] = 0.f; D[m][j][1] = 0.f; D[m][j][2] = 0.f; D[m][j][3] = 0.f;
            }
        const uint4* wbL = g_wb + (size_t)L * (8 * 16 * 32);
        #pragma unroll
        for (int q = 0; q < 8; q++) {
            uint4 B[4];
            #pragma unroll
            for (int j = 0; j < 4; j++) B[j] = wbL[(q * 16 + nh * 4 + j) * 32 + lane];
            #pragma unroll
            for (int m = 0; m < 4; m++) {
                const uint4* ap = Asm + ((q * 4 + m) * 2) * 32;
                uint4 h = ap[lane];
                uint4 l = ap[32 + lane];
                mma_m(D[m], h, l, B);
            }
        }
        __syncthreads();   // all A reads done before overwrite
        epilogue_sts(D, Asm, (L == 0) ? b1 : b2, nh, t, lane);
        __syncthreads();   // writes visible to all warps
    }

    // ---- layer 3 (w3) + fused layer 4 (w4, partial over this warp's n-quarter) ----
    {
        #pragma unroll
        for (int m = 0; m < 4; m++)
            #pragma unroll
            for (int j = 0; j < 4; j++) {
                D[m][j][0] = 0.f; D[m][j][1] = 0.f; D[m][j][2] = 0.f; D[m][j][3] = 0.f;
            }
        const uint4* wbL = g_wb + (size_t)2 * (8 * 16 * 32);
        #pragma unroll
        for (int q = 0; q < 8; q++) {
            uint4 B[4];
            #pragma unroll
            for (int j = 0; j < 4; j++) B[j] = wbL[(q * 16 + nh * 4 + j) * 32 + lane];
            #pragma unroll
            for (int m = 0; m < 4; m++) {
                const uint4* ap = Asm + ((q * 4 + m) * 2) * 32;
                uint4 h = ap[lane];
                uint4 l = ap[32 + lane];
                mma_m(D[m], h, l, B);
            }
        }

        float m0g[4], m1g[4], m0h[4], m1h[4];
        #pragma unroll
        for (int m = 0; m < 4; m++) { m0g[m] = 0.f; m1g[m] = 0.f; m0h[m] = 0.f; m1h[m] = 0.f; }
        #pragma unroll
        for (int j = 0; j < 4; j++) {
            int n0 = (nh * 4 + j) * 8 + t * 2;
            float2 bj = *(const float2*)(b3 + n0);
            float4 w4v = *(const float4*)(w4 + 2 * n0);
            #pragma unroll
            for (int m = 0; m < 4; m++) {
                float v0 = fmaxf(D[m][j][0] + bj.x, 0.f);
                float v1 = fmaxf(D[m][j][1] + bj.y, 0.f);
                float v2 = fmaxf(D[m][j][2] + bj.x, 0.f);
                float v3 = fmaxf(D[m][j][3] + bj.y, 0.f);
                m0g[m] = fmaf(v0, w4v.x, fmaf(v1, w4v.z, m0g[m]));
                m1g[m] = fmaf(v0, w4v.y, fmaf(v1, w4v.w, m1g[m]));
                m0h[m] = fmaf(v2, w4v.x, fmaf(v3, w4v.z, m0h[m]));
                m1h[m] = fmaf(v2, w4v.y, fmaf(v3, w4v.w, m1h[m]));
            }
        }
        #pragma unroll
        for (int d = 1; d <= 2; d <<= 1) {
            #pragma unroll
            for (int m = 0; m < 4; m++) {
                m0g[m] += __shfl_xor_sync(0xFFFFFFFFu, m0g[m], d);
                m1g[m] += __shfl_xor_sync(0xFFFFFFFFu, m1g[m], d);
                m0h[m] += __shfl_xor_sync(0xFFFFFFFFu, m0h[m], d);
                m1h[m] += __shfl_xor_sync(0xFFFFFFFFu, m1h[m], d);
            }
        }
        if (t == 0) {
            // bias added once per edge (by warp nh == 0)
            float bb0 = (nh == 0) ? b4[0] : 0.f;
            float bb1 = (nh == 0) ? b4[1] : 0.f;
            #pragma unroll
            for (int m = 0; m < 4; m++) {
                int d0 = sdst[m * 16 + g];
                if (d0 >= 0) {
                    atomicAdd(&out[2 * d0],     m0g[m] + bb0);
                    atomicAdd(&out[2 * d0 + 1], m1g[m] + bb1);
                }
                int d1 = sdst[m * 16 + g + 8];
                if (d1 >= 0) {
                    atomicAdd(&out[2 * d1],     m0h[m] + bb0);
                    atomicAdd(&out[2 * d1 + 1], m1h[m] + bb1);
                }
            }
        }
    }
}

extern "C" void kernel_launch(void* const* d_in, const int* in_sizes, int n_in,
                              void* d_out, int out_size) {
    const float* pos   = (const float*)d_in[0];
    const float* vel   = (const float*)d_in[1];
    const float* a     = (const float*)d_in[2];
    const float* vnorm = (const float*)d_in[3];
    const float* w0    = (const float*)d_in[4];
    const float* b0    = (const float*)d_in[5];
    const float* w1    = (const float*)d_in[6];
    const float* b1    = (const float*)d_in[7];
    const float* w2    = (const float*)d_in[8];
    const float* b2    = (const float*)d_in[9];
    const float* w3    = (const float*)d_in[10];
    const float* b3    = (const float*)d_in[11];
    const float* w4    = (const float*)d_in[12];
    const float* b4    = (const float*)d_in[13];
    const int*   ei    = (const int*)d_in[14];    // int32 [2, E]
    const int*   did   = (const int*)d_in[15];
    float*       out   = (float*)d_out;

    int E = in_sizes[14] / 2;
    int N = in_sizes[0] / 2;

    int prep_n = (out_size > NFRAG) ? out_size : NFRAG;
    prep_kernel<<<(prep_n + 255) / 256, 256>>>(w0, w1, w2, w3, out, out_size);

    int tiles = (E + TILE - 1) / TILE;
    gnn_mma_kernel<<<tiles, NTHREADS>>>(
        pos, vel, a, vnorm, b0, b1, b2, b3, w4, b4,
        ei, did, out, E, N);
}